// round 5
// baseline (speedup 1.0000x reference)
#include <cuda_runtime.h>
#include <cstdint>

#define F 128
#define F4 32
#define MAX_ATOMS 20000
#define MAX_PAIRS 320000
#define SCAN_THREADS 1024
#define SCAN_PER ((MAX_ATOMS + SCAN_THREADS - 1) / SCAN_THREADS)   // 20

#define GA 16               // atoms per tile
#define VS_STRIDE 130       // u64 stride per V row (48 rows per buffer)
#define REC 64              // record staging per producer warp
#define NPROD 128           // producer threads (warps 0-3)

typedef unsigned long long u64;

// Scratch (allocation-free rule: __device__ globals; zero-initialized at load)
__device__ float  g_Wt[F * F];       // Wt[f][g] = W[g][f]
__device__ int    g_cnt[MAX_ATOMS];  // pairs per atom (re-zeroed each run by fused kernel)
__device__ int    g_off[MAX_ATOMS];
__device__ int    g_pos[MAX_PAIRS];
__device__ int    g_recJ[MAX_PAIRS];
__device__ float4 g_recU[MAX_PAIRS]; // (ux*c, uy*c, uz*c, c)

__device__ __forceinline__ u64 pack64(float a, float b) {
    u64 r; asm("mov.b64 %0, {%1, %2};" : "=l"(r) : "f"(a), "f"(b)); return r;
}
__device__ __forceinline__ float2 unpack64(u64 v) {
    float2 r; asm("mov.b64 {%0, %1}, %2;" : "=f"(r.x), "=f"(r.y) : "l"(v)); return r;
}
#define FMA2(acc, a, b) asm("fma.rn.f32x2 %0, %1, %2, %0;" : "+l"(acc) : "l"(a), "l"(b))

#define BAR_SYNC(id) asm volatile("bar.sync %0, %1;"   :: "r"(id), "r"(256) : "memory")
#define BAR_ARR(id)  asm volatile("bar.arrive %0, %1;" :: "r"(id), "r"(256) : "memory")

// ---------------------------------------------------------------------------
// K1: prep = W transpose + histogram (+ per-pair within-bin position)
// g_cnt is guaranteed zero on entry (module-load zero-init; fused kernel
// re-zeroes it after reading, every run).
// ---------------------------------------------------------------------------
__global__ void prep_kernel(const float* __restrict__ Wm,
                            const int* __restrict__ pl, int n_pairs) {
    int idx = blockIdx.x * blockDim.x + threadIdx.x;
    if (idx < F * F) {
        int f = idx >> 7, g = idx & (F - 1);
        g_Wt[idx] = Wm[g * F + f];
    }
    if (idx < n_pairs) g_pos[idx] = atomicAdd(&g_cnt[pl[idx]], 1);
}

// ---------------------------------------------------------------------------
// K2: exclusive scan over g_cnt -> g_off (single block)
// ---------------------------------------------------------------------------
__global__ void scan_kernel(int n_atoms) {
    __shared__ int ssum[SCAN_THREADS];
    int t = threadIdx.x;
    int base = t * SCAN_PER;
    int local[SCAN_PER];
    int s = 0;
#pragma unroll
    for (int k = 0; k < SCAN_PER; k++) {
        int idx = base + k;
        int v = (idx < n_atoms) ? g_cnt[idx] : 0;
        local[k] = s;
        s += v;
    }
    ssum[t] = s;
    __syncthreads();
    for (int d = 1; d < SCAN_THREADS; d <<= 1) {
        int x = (t >= d) ? ssum[t - d] : 0;
        __syncthreads();
        ssum[t] += x;
        __syncthreads();
    }
    int excl = (t > 0) ? ssum[t - 1] : 0;
#pragma unroll
    for (int k = 0; k < SCAN_PER; k++) {
        int idx = base + k;
        if (idx < n_atoms) g_off[idx] = excl + local[k];
    }
}

// ---------------------------------------------------------------------------
// K3: scatter pairs into bins; record stores PRE-SCALED (u*c, c) so the
// gather needs only 8 FMA2 per pair.
// ---------------------------------------------------------------------------
__global__ void scatter_kernel(const int* __restrict__ pl,
                               const float* __restrict__ cut,
                               const float* __restrict__ rij,
                               int n_pairs) {
    int p = blockIdx.x * blockDim.x + threadIdx.x;
    if (p >= n_pairs) return;
    int   i = pl[p];
    int   j = pl[n_pairs + p];
    float c = cut[p];
    float r0 = rij[3 * p + 0];
    float r1 = rij[3 * p + 1];
    float r2 = rij[3 * p + 2];
    float s = rsqrtf(r0 * r0 + r1 * r1 + r2 * r2) * c;
    int pos = g_off[i] + g_pos[p];
    g_recJ[pos] = j;
    g_recU[pos] = make_float4(r0 * s, r1 * s, r2 * s, c);
}

// ---------------------------------------------------------------------------
// K4: fused warp-specialized gather + GEMM + norm.
// Warps 0-3 = producers: gather pairs, accumulate radial (-> gmem) and the
// 3 vector channels; write V tile DUPLICATED (v,v) into smem double buffer.
// Warps 4-7 = consumers: FFMA2 GEMM against W (staged once) + norm epilogue.
// Handoff via named barriers (bar.arrive by writer, bar.sync by waiter).
// ---------------------------------------------------------------------------
struct Acc8 { u64 r0, r1, x0, x1, y0, y1, z0, z1; };

__device__ __forceinline__ void store_dup(u64* dst, u64 a, u64 b) {
    float2 pa = unpack64(a), pb = unpack64(b);
    ulonglong2 q0, q1;
    q0.x = pack64(pa.x, pa.x); q0.y = pack64(pa.y, pa.y);
    q1.x = pack64(pb.x, pb.x); q1.y = pack64(pb.y, pb.y);
    *(ulonglong2*)(dst)     = q0;
    *(ulonglong2*)(dst + 2) = q1;
}

#define LOADB(buf, k0)                                                  \
    do {                                                                \
        _Pragma("unroll")                                               \
        for (int q = 0; q < 8; q++) {                                   \
            int idx_ = (k0) + q;                                        \
            if (idx_ < m) buf[q] = __ldg(&A2[mJ[idx_] * F4 + lane]);    \
        }                                                               \
    } while (0)

#define COMPB(buf, k0)                                                  \
    do {                                                                \
        _Pragma("unroll")                                               \
        for (int q = 0; q < 8; q++) {                                   \
            int idx_ = (k0) + q;                                        \
            if (idx_ < m) {                                             \
                float4 u = mU[idx_];                                    \
                u64 cc = pack64(u.w, u.w);                              \
                u64 xx = pack64(u.x, u.x);                              \
                u64 yy = pack64(u.y, u.y);                              \
                u64 zz = pack64(u.z, u.z);                              \
                FMA2(s.r0, cc, buf[q].x); FMA2(s.r1, cc, buf[q].y);     \
                FMA2(s.x0, xx, buf[q].x); FMA2(s.x1, xx, buf[q].y);     \
                FMA2(s.y0, yy, buf[q].x); FMA2(s.y1, yy, buf[q].y);     \
                FMA2(s.z0, zz, buf[q].x); FMA2(s.z1, zz, buf[q].y);     \
            }                                                           \
        }                                                               \
    } while (0)

__global__ __launch_bounds__(256, 1)
void fused_kernel(const ulonglong2* __restrict__ A2,
                  const float* __restrict__ bias,
                  float* __restrict__ out, int n_atoms) {
    extern __shared__ char sm[];
    float*  Ws   = (float*)sm;                                   // 64KB
    u64*    VsU  = (u64*)(sm + F * F * 4);                        // 2 x 48 x 130 u64
    int*    sJ   = (int*)(sm + F * F * 4 + 2 * 48 * VS_STRIDE * 8);
    float4* sU   = (float4*)((char*)sJ + 4 * REC * 4);
    int*    scnt = (int*)((char*)sU + 4 * REC * 16);              // 2 x 16

    int t = threadIdx.x;

    // stage W^T once per block
    {
        const float4* s4 = (const float4*)g_Wt;
        float4* d4 = (float4*)Ws;
        for (int k = t; k < F * F / 4; k += 256) d4[k] = s4[k];
    }
    __syncthreads();

    int tiles = (n_atoms + GA - 1) / GA;
    int tile_it = 0;

    if (t < NPROD) {
        // ------------------------- PRODUCER -------------------------
        int pw = t >> 5, lane = t & 31;
        int*    mJ = sJ + pw * REC;
        float4* mU = sU + pw * REC;

        for (int tile = blockIdx.x; tile < tiles; tile += gridDim.x, tile_it++) {
            int buf = tile_it & 1;
            if (tile_it >= 2) BAR_SYNC(3 + buf);
            u64* vbuf = VsU + buf * 48 * VS_STRIDE;

#pragma unroll 1
            for (int k = 0; k < 4; k++) {
                int atil = pw * 4 + k;
                int atom = tile * GA + atil;
                if (atom >= n_atoms) continue;
                int n = g_cnt[atom];
                int base = g_off[atom];
                if (lane == 0) { g_cnt[atom] = 0; scnt[buf * GA + atil] = n; }

                Acc8 s = {0, 0, 0, 0, 0, 0, 0, 0};

                for (int c0 = 0; c0 < n; c0 += REC) {
                    int m = n - c0; if (m > REC) m = REC;
                    if (lane < m)      { mJ[lane]      = g_recJ[base + c0 + lane];
                                         mU[lane]      = g_recU[base + c0 + lane]; }
                    if (lane + 32 < m) { mJ[lane + 32] = g_recJ[base + c0 + lane + 32];
                                         mU[lane + 32] = g_recU[base + c0 + lane + 32]; }
                    __syncwarp();

                    ulonglong2 b0[8], b1[8];
                    LOADB(b0, 0);
                    for (int k0 = 0; k0 < m; k0 += 16) {
                        LOADB(b1, k0 + 8);
                        COMPB(b0, k0);
                        LOADB(b0, k0 + 16);
                        COMPB(b1, k0 + 8);
                    }
                    __syncwarp();
                }

                // radial half of output
                float2 p0 = unpack64(s.r0), p1 = unpack64(s.r1);
                *(float4*)&out[atom * (2 * F) + F + lane * 4] =
                    make_float4(p0.x, p0.y, p1.x, p1.y);
                // V channels, duplicated (v,v)
                store_dup(vbuf + (atil * 3 + 0) * VS_STRIDE + 4 * lane, s.x0, s.x1);
                store_dup(vbuf + (atil * 3 + 1) * VS_STRIDE + 4 * lane, s.y0, s.y1);
                store_dup(vbuf + (atil * 3 + 2) * VS_STRIDE + 4 * lane, s.z0, s.z1);
            }
            __threadfence_block();
            BAR_ARR(1 + buf);
        }
    } else {
        // ------------------------- CONSUMER -------------------------
        int tc = t - NPROD;
        int ga8 = tc & 7;            // atom within sub-tile
        int cgi = tc >> 3;           // col group (0..15) -> cols cgi*8..+7
        const ulonglong2* WsU2 = (const ulonglong2*)Ws;   // 32 per row

        for (int tile = blockIdx.x; tile < tiles; tile += gridDim.x, tile_it++) {
            int buf = tile_it & 1;
            BAR_SYNC(1 + buf);
            const u64* vbuf = VsU + buf * 48 * VS_STRIDE;

#pragma unroll 1
            for (int sub = 0; sub < 2; sub++) {
                int atil = sub * 8 + ga8;
                int atom = tile * GA + atil;
                u64 acc[3][4] = {};

#pragma unroll 4
                for (int f = 0; f < F; f += 2) {
                    ulonglong2 wa0 = WsU2[f * 32 + cgi * 2];
                    ulonglong2 wa1 = WsU2[f * 32 + cgi * 2 + 1];
                    ulonglong2 wb0 = WsU2[(f + 1) * 32 + cgi * 2];
                    ulonglong2 wb1 = WsU2[(f + 1) * 32 + cgi * 2 + 1];
#pragma unroll
                    for (int c = 0; c < 3; c++) {
                        ulonglong2 v = *(const ulonglong2*)&vbuf[(atil * 3 + c) * VS_STRIDE + f];
                        FMA2(acc[c][0], v.x, wa0.x);
                        FMA2(acc[c][1], v.x, wa0.y);
                        FMA2(acc[c][2], v.x, wa1.x);
                        FMA2(acc[c][3], v.x, wa1.y);
                        FMA2(acc[c][0], v.y, wb0.x);
                        FMA2(acc[c][1], v.y, wb0.y);
                        FMA2(acc[c][2], v.y, wb1.x);
                        FMA2(acc[c][3], v.y, wb1.y);
                    }
                }

                if (atom < n_atoms) {
                    float cnt = (float)scnt[buf * GA + atil];
                    int cb = cgi * 8;
                    float4 bv0 = __ldg((const float4*)&bias[cb]);
                    float4 bv1 = __ldg((const float4*)&bias[cb + 4]);
                    float bb[8];
                    bb[0] = bv0.x * cnt; bb[1] = bv0.y * cnt;
                    bb[2] = bv0.z * cnt; bb[3] = bv0.w * cnt;
                    bb[4] = bv1.x * cnt; bb[5] = bv1.y * cnt;
                    bb[6] = bv1.z * cnt; bb[7] = bv1.w * cnt;
                    float ob[8];
#pragma unroll
                    for (int q = 0; q < 4; q++) {
                        float2 vx = unpack64(acc[0][q]);
                        float2 vy = unpack64(acc[1][q]);
                        float2 vz = unpack64(acc[2][q]);
                        float x0 = vx.x + bb[2 * q], y0 = vy.x + bb[2 * q], z0 = vz.x + bb[2 * q];
                        float x1 = vx.y + bb[2 * q + 1], y1 = vy.y + bb[2 * q + 1], z1 = vz.y + bb[2 * q + 1];
                        ob[2 * q]     = sqrtf(x0 * x0 + y0 * y0 + z0 * z0 + 1e-12f);
                        ob[2 * q + 1] = sqrtf(x1 * x1 + y1 * y1 + z1 * z1 + 1e-12f);
                    }
                    float* o = &out[atom * (2 * F) + cb];
                    *(float4*)o       = make_float4(ob[0], ob[1], ob[2], ob[3]);
                    *(float4*)(o + 4) = make_float4(ob[4], ob[5], ob[6], ob[7]);
                }
            }
            BAR_ARR(3 + buf);
        }
    }
}

// ---------------------------------------------------------------------------
// Launch (4 kernels)
// ---------------------------------------------------------------------------
extern "C" void kernel_launch(void* const* d_in, const int* in_sizes, int n_in,
                              void* d_out, int out_size) {
    const float* A   = (const float*)d_in[0];   // [N, F]
    const int*   pl  = (const int*)  d_in[1];   // [2, P]
    const float* cut = (const float*)d_in[2];   // [P, 1]
    const float* rij = (const float*)d_in[3];   // [P, 3]
    const float* Wm  = (const float*)d_in[4];   // [F, F]
    const float* b   = (const float*)d_in[5];   // [F]
    float* out = (float*)d_out;                 // [N, 2F]

    int n_atoms = in_sizes[0] / F;
    int n_pairs = in_sizes[2];

    int prep_n = (n_pairs > F * F) ? n_pairs : F * F;
    prep_kernel<<<(prep_n + 255) / 256, 256>>>(Wm, pl, n_pairs);

    scan_kernel<<<1, SCAN_THREADS>>>(n_atoms);

    scatter_kernel<<<(n_pairs + 255) / 256, 256>>>(pl, cut, rij, n_pairs);

    {
        int smem = F * F * 4                    // Ws
                 + 2 * 48 * VS_STRIDE * 8       // V double buffer
                 + 4 * REC * 4                  // sJ
                 + 4 * REC * 16                 // sU
                 + 2 * GA * 4;                  // scnt
        cudaFuncSetAttribute(fused_kernel,
                             cudaFuncAttributeMaxDynamicSharedMemorySize, smem);
        fused_kernel<<<148, 256, smem>>>((const ulonglong2*)A, b, out, n_atoms);
    }
}

// round 7
// speedup vs baseline: 1.3607x; 1.3607x over previous
#include <cuda_runtime.h>
#include <cstdint>

#define F 128
#define F4 32
#define MAX_ATOMS 20000
#define MAX_PAIRS 320000
#define SCAN_THREADS 1024
#define SCAN_PER ((MAX_ATOMS + SCAN_THREADS - 1) / SCAN_THREADS)   // 20

// GEMM tile config: 16 atoms (48 rows) per tile, 256 threads
#define GA 16
#define GT 256
#define VS_STRIDE 130        // u64 row stride

#define REC 32               // record staging per gather warp

typedef unsigned long long u64;

// Scratch (allocation-free rule: __device__ globals; zero-init at load,
// g_cnt is restored to zero by scan_kernel every run)
__device__ float4     g_V[MAX_ATOMS * 3 * F4];     // V[i][c][:] accumulators (f4 units)
__device__ float      g_Wt[F * F];                 // Wt[f][g] = W[g][f]
__device__ int        g_cnt[MAX_ATOMS];            // hist counters (self-zeroing)
__device__ int        g_cnt2[MAX_ATOMS];           // stable copy of counts
__device__ int        g_off[MAX_ATOMS];            // bin offsets
__device__ int        g_pos[MAX_PAIRS];            // within-bin position
__device__ int        g_recJ[MAX_PAIRS];           // binned neighbor index
__device__ ulonglong4 g_recP[MAX_PAIRS];           // packed ((xc,xc),(yc,yc),(zc,zc),(c,c))

__device__ __forceinline__ u64 pack64(float a, float b) {
    u64 r; asm("mov.b64 %0, {%1, %2};" : "=l"(r) : "f"(a), "f"(b)); return r;
}
__device__ __forceinline__ float2 unpack64(u64 v) {
    float2 r; asm("mov.b64 {%0, %1}, %2;" : "=f"(r.x), "=f"(r.y) : "l"(v)); return r;
}
#define FMA2(acc, a, b) asm("fma.rn.f32x2 %0, %1, %2, %0;" : "+l"(acc) : "l"(a), "l"(b))

// ---------------------------------------------------------------------------
// K1: prep = W transpose + histogram + within-bin positions
// (g_cnt is zero on entry: zero-init first run, re-zeroed by scan after)
// ---------------------------------------------------------------------------
__global__ void prep_kernel(const float* __restrict__ Wm,
                            const int* __restrict__ pl, int n_pairs) {
    int idx = blockIdx.x * blockDim.x + threadIdx.x;
    if (idx < F * F) {
        int f = idx >> 7, g = idx & (F - 1);
        g_Wt[idx] = Wm[g * F + f];
    }
    if (idx < n_pairs) g_pos[idx] = atomicAdd(&g_cnt[pl[idx]], 1);
}

// ---------------------------------------------------------------------------
// K2: exclusive scan g_cnt -> g_off; copy counts to g_cnt2; zero g_cnt
// ---------------------------------------------------------------------------
__global__ void scan_kernel(int n_atoms) {
    __shared__ int ssum[SCAN_THREADS];
    int t = threadIdx.x;
    int base = t * SCAN_PER;
    int local[SCAN_PER];
    int s = 0;
#pragma unroll
    for (int k = 0; k < SCAN_PER; k++) {
        int idx = base + k;
        int v = 0;
        if (idx < n_atoms) {
            v = g_cnt[idx];
            g_cnt[idx] = 0;        // restore for next run
            g_cnt2[idx] = v;       // stable copy
        }
        local[k] = s;
        s += v;
    }
    ssum[t] = s;
    __syncthreads();
    for (int d = 1; d < SCAN_THREADS; d <<= 1) {
        int x = (t >= d) ? ssum[t - d] : 0;
        __syncthreads();
        ssum[t] += x;
        __syncthreads();
    }
    int excl = (t > 0) ? ssum[t - 1] : 0;
#pragma unroll
    for (int k = 0; k < SCAN_PER; k++) {
        int idx = base + k;
        if (idx < n_atoms) g_off[idx] = excl + local[k];
    }
}

// ---------------------------------------------------------------------------
// K3: scatter pairs into bins; records PRE-SCALED and PRE-PACKED for f32x2
// ---------------------------------------------------------------------------
__global__ void scatter_kernel(const int* __restrict__ pl,
                               const float* __restrict__ cut,
                               const float* __restrict__ rij,
                               int n_pairs) {
    int p = blockIdx.x * blockDim.x + threadIdx.x;
    if (p >= n_pairs) return;
    int   i = pl[p];
    int   j = pl[n_pairs + p];
    float c = cut[p];
    float r0 = rij[3 * p + 0];
    float r1 = rij[3 * p + 1];
    float r2 = rij[3 * p + 2];
    float s = rsqrtf(r0 * r0 + r1 * r1 + r2 * r2) * c;
    int pos = g_off[i] + g_pos[p];
    float xc = r0 * s, yc = r1 * s, zc = r2 * s;
    ulonglong4 rec;
    rec.x = pack64(xc, xc);
    rec.y = pack64(yc, yc);
    rec.z = pack64(zc, zc);
    rec.w = pack64(c, c);
    g_recJ[pos] = j;
    g_recP[pos] = rec;
}

// ---------------------------------------------------------------------------
// K4: gather. One warp per atom; records staged in smem; 8-wide
// double-buffered A prefetch; 8 FMA2 per pair.
// ---------------------------------------------------------------------------
struct Acc8 { u64 r0, r1, x0, x1, y0, y1, z0, z1; };

#define LOADB(buf, k0)                                                   \
    do {                                                                 \
        _Pragma("unroll")                                                \
        for (int q = 0; q < 8; q++) {                                    \
            int idx_ = (k0) + q;                                         \
            if (idx_ < m) buf[q] = __ldg(&A2[mJ[idx_] * F4 + lane]);     \
        }                                                                \
    } while (0)

#define COMPB(buf, k0)                                                   \
    do {                                                                 \
        _Pragma("unroll")                                                \
        for (int q = 0; q < 8; q++) {                                    \
            int idx_ = (k0) + q;                                         \
            if (idx_ < m) {                                              \
                ulonglong4 u = mP[idx_];                                 \
                FMA2(s.r0, u.w, buf[q].x); FMA2(s.r1, u.w, buf[q].y);    \
                FMA2(s.x0, u.x, buf[q].x); FMA2(s.x1, u.x, buf[q].y);    \
                FMA2(s.y0, u.y, buf[q].x); FMA2(s.y1, u.y, buf[q].y);    \
                FMA2(s.z0, u.z, buf[q].x); FMA2(s.z1, u.z, buf[q].y);    \
            }                                                            \
        }                                                                \
    } while (0)

__global__ __launch_bounds__(256)
void gather_kernel(const ulonglong2* __restrict__ A2,
                   float* __restrict__ out, int n_atoms) {
    __shared__ int        sJ[8][REC];
    __shared__ ulonglong4 sP[8][REC];

    int warp = threadIdx.x >> 5, lane = threadIdx.x & 31;
    int w = blockIdx.x * 8 + warp;
    if (w >= n_atoms) return;
    int n = g_cnt2[w];
    int base = g_off[w];
    int*        mJ = sJ[warp];
    ulonglong4* mP = sP[warp];

    Acc8 s = {0, 0, 0, 0, 0, 0, 0, 0};

    for (int c0 = 0; c0 < n; c0 += REC) {
        int m = n - c0; if (m > REC) m = REC;
        if (lane < m) {
            mJ[lane] = g_recJ[base + c0 + lane];
            mP[lane] = g_recP[base + c0 + lane];
        }
        __syncwarp();

        ulonglong2 b0[8], b1[8];
        LOADB(b0, 0);
        for (int k0 = 0; k0 < m; k0 += 16) {
            LOADB(b1, k0 + 8);
            COMPB(b0, k0);
            LOADB(b0, k0 + 16);
            COMPB(b1, k0 + 8);
        }
        __syncwarp();
    }

    float2 p0, p1;
    p0 = unpack64(s.r0); p1 = unpack64(s.r1);
    *(float4*)&out[w * (2 * F) + F + lane * 4] = make_float4(p0.x, p0.y, p1.x, p1.y);
    p0 = unpack64(s.x0); p1 = unpack64(s.x1);
    g_V[(w * 3 + 0) * F4 + lane] = make_float4(p0.x, p0.y, p1.x, p1.y);
    p0 = unpack64(s.y0); p1 = unpack64(s.y1);
    g_V[(w * 3 + 1) * F4 + lane] = make_float4(p0.x, p0.y, p1.x, p1.y);
    p0 = unpack64(s.z0); p1 = unpack64(s.z1);
    g_V[(w * 3 + 2) * F4 + lane] = make_float4(p0.x, p0.y, p1.x, p1.y);
}

// ---------------------------------------------------------------------------
// K5: fused GEMM + norm (proven R4 version; counts from g_cnt2)
// ---------------------------------------------------------------------------
__global__ void gemm_norm_kernel(const float* __restrict__ bias,
                                 float* __restrict__ out, int n_atoms) {
    extern __shared__ char smraw[];
    float* Ws = (float*)smraw;                        // [F][F] floats
    u64*   VsU = (u64*)(smraw + F * F * 4);           // [48][VS_STRIDE] dup (v,v)

    int t = threadIdx.x;
    int ga = t & 15;            // atom in tile
    int cg = t >> 4;            // col group (0..15) -> cols cg*8..+7
    const ulonglong2* WsU2 = (const ulonglong2*)Ws;   // row stride 32 ull2

    {
        const float4* src = (const float4*)g_Wt;
        float4* dst = (float4*)Ws;
        for (int k = t; k < F * F / 4; k += GT) dst[k] = src[k];
    }
    __syncthreads();

    int nrows3 = n_atoms * 3;
    int tiles = (n_atoms + GA - 1) / GA;
    for (int tile = blockIdx.x; tile < tiles; tile += gridDim.x) {
        int row0 = tile * GA * 3;

        float4 vst[6];
#pragma unroll
        for (int r = 0; r < 6; r++) {
            int idx = t + r * GT;            // 0..1535
            int row = idx >> 5, f4 = idx & 31;
            int grow = row0 + row;
            vst[r] = (grow < nrows3)
                       ? __ldg(&g_V[grow * F4 + f4])
                       : make_float4(0.f, 0.f, 0.f, 0.f);
        }
        __syncthreads();
#pragma unroll
        for (int r = 0; r < 6; r++) {
            int idx = t + r * GT;
            int row = idx >> 5, f4 = idx & 31;
            ulonglong2 q0, q1;
            q0.x = pack64(vst[r].x, vst[r].x);
            q0.y = pack64(vst[r].y, vst[r].y);
            q1.x = pack64(vst[r].z, vst[r].z);
            q1.y = pack64(vst[r].w, vst[r].w);
            *(ulonglong2*)&VsU[row * VS_STRIDE + f4 * 4]     = q0;
            *(ulonglong2*)&VsU[row * VS_STRIDE + f4 * 4 + 2] = q1;
        }
        __syncthreads();

        u64 acc[3][4] = {};
#pragma unroll 4
        for (int f = 0; f < F; f += 2) {
            ulonglong2 wa0 = WsU2[f * 32 + cg * 2];
            ulonglong2 wa1 = WsU2[f * 32 + cg * 2 + 1];
            ulonglong2 wb0 = WsU2[(f + 1) * 32 + cg * 2];
            ulonglong2 wb1 = WsU2[(f + 1) * 32 + cg * 2 + 1];
#pragma unroll
            for (int c = 0; c < 3; c++) {
                ulonglong2 v = *(const ulonglong2*)&VsU[(ga * 3 + c) * VS_STRIDE + f];
                FMA2(acc[c][0], v.x, wa0.x);
                FMA2(acc[c][1], v.x, wa0.y);
                FMA2(acc[c][2], v.x, wa1.x);
                FMA2(acc[c][3], v.x, wa1.y);
                FMA2(acc[c][0], v.y, wb0.x);
                FMA2(acc[c][1], v.y, wb0.y);
                FMA2(acc[c][2], v.y, wb1.x);
                FMA2(acc[c][3], v.y, wb1.y);
            }
        }

        int atom = tile * GA + ga;
        if (atom < n_atoms) {
            float cnt = (float)g_cnt2[atom];
            float4 bv0 = __ldg((const float4*)&bias[cg * 8]);
            float4 bv1 = __ldg((const float4*)&bias[cg * 8 + 4]);
            float ob[8], bb[8];
            bb[0] = bv0.x * cnt; bb[1] = bv0.y * cnt; bb[2] = bv0.z * cnt; bb[3] = bv0.w * cnt;
            bb[4] = bv1.x * cnt; bb[5] = bv1.y * cnt; bb[6] = bv1.z * cnt; bb[7] = bv1.w * cnt;
#pragma unroll
            for (int q = 0; q < 4; q++) {
                float2 vx = unpack64(acc[0][q]);
                float2 vy = unpack64(acc[1][q]);
                float2 vz = unpack64(acc[2][q]);
                float x0 = vx.x + bb[2 * q], y0 = vy.x + bb[2 * q], z0 = vz.x + bb[2 * q];
                float x1 = vx.y + bb[2 * q + 1], y1 = vy.y + bb[2 * q + 1], z1 = vz.y + bb[2 * q + 1];
                ob[2 * q]     = sqrtf(x0 * x0 + y0 * y0 + z0 * z0 + 1e-12f);
                ob[2 * q + 1] = sqrtf(x1 * x1 + y1 * y1 + z1 * z1 + 1e-12f);
            }
            float* o = &out[atom * (2 * F) + cg * 8];
            *(float4*)o       = make_float4(ob[0], ob[1], ob[2], ob[3]);
            *(float4*)(o + 4) = make_float4(ob[4], ob[5], ob[6], ob[7]);
        }
    }
}

// ---------------------------------------------------------------------------
// Launch (5 kernels)
// ---------------------------------------------------------------------------
extern "C" void kernel_launch(void* const* d_in, const int* in_sizes, int n_in,
                              void* d_out, int out_size) {
    const float* A   = (const float*)d_in[0];   // [N, F]
    const int*   pl  = (const int*)  d_in[1];   // [2, P]
    const float* cut = (const float*)d_in[2];   // [P, 1]
    const float* rij = (const float*)d_in[3];   // [P, 3]
    const float* Wm  = (const float*)d_in[4];   // [F, F]
    const float* b   = (const float*)d_in[5];   // [F]
    float* out = (float*)d_out;                 // [N, 2F]

    int n_atoms = in_sizes[0] / F;
    int n_pairs = in_sizes[2];

    int prep_n = (n_pairs > F * F) ? n_pairs : F * F;
    prep_kernel<<<(prep_n + 255) / 256, 256>>>(Wm, pl, n_pairs);

    scan_kernel<<<1, SCAN_THREADS>>>(n_atoms);

    scatter_kernel<<<(n_pairs + 255) / 256, 256>>>(pl, cut, rij, n_pairs);

    gather_kernel<<<(n_atoms + 7) / 8, 256>>>((const ulonglong2*)A, out, n_atoms);

    {
        int smem = F * F * 4 + 3 * GA * VS_STRIDE * 8;   // 64KB + 49.9KB
        cudaFuncSetAttribute(gemm_norm_kernel,
                             cudaFuncAttributeMaxDynamicSharedMemorySize, smem);
        gemm_norm_kernel<<<296, GT, smem>>>(b, out, n_atoms);
    }
}

// round 8
// speedup vs baseline: 1.7056x; 1.2535x over previous
#include <cuda_runtime.h>
#include <cstdint>

#define F 128
#define F4 (F/4)
#define MAX_ATOMS 20000
#define MAX_PAIRS 320000
#define SCAN_THREADS 1024
#define SCAN_PER ((MAX_ATOMS + SCAN_THREADS - 1) / SCAN_THREADS)   // 20

// GEMM tile config: 32 atoms (96 rows) per tile, 512 threads
#define GA 32
#define GT 512
#define VS_STRIDE 130        // u64 row stride

typedef unsigned long long u64;

// Scratch (allocation-free rule: __device__ globals)
__device__ float4 g_V[MAX_ATOMS * 3 * F4];     // V[i][c][:] accumulators
__device__ float  g_Wt[F * F];                 // Wt[f][g] = W[g][f]
__device__ int    g_cnt[MAX_ATOMS];            // pairs per atom
__device__ int    g_off[MAX_ATOMS];            // bin start offsets
__device__ int    g_pos[MAX_PAIRS];            // position of pair within its bin
__device__ int    g_recJ[MAX_PAIRS];           // binned: neighbor index j
__device__ float4 g_recU[MAX_PAIRS];           // binned: (ux*c, uy*c, uz*c, c)

__device__ __forceinline__ u64 pack64(float a, float b) {
    u64 r; asm("mov.b64 %0, {%1, %2};" : "=l"(r) : "f"(a), "f"(b)); return r;
}
__device__ __forceinline__ float2 unpack64(u64 v) {
    float2 r; asm("mov.b64 {%0, %1}, %2;" : "=f"(r.x), "=f"(r.y) : "l"(v)); return r;
}
__device__ __forceinline__ u64 mul2(u64 a, u64 b) {
    u64 r; asm("mul.rn.f32x2 %0, %1, %2;" : "=l"(r) : "l"(a), "l"(b)); return r;
}
__device__ __forceinline__ u64 add2(u64 a, u64 b) {
    u64 r; asm("add.rn.f32x2 %0, %1, %2;" : "=l"(r) : "l"(a), "l"(b)); return r;
}
#define FMA2(acc, a, b) asm("fma.rn.f32x2 %0, %1, %2, %0;" : "+l"(acc) : "l"(a), "l"(b))

// ---------------------------------------------------------------------------
// K1: zero counters + transpose W once (Wt[f][g] = W[g][f])
// ---------------------------------------------------------------------------
__global__ void init_kernel(const float* __restrict__ Wm, int n_atoms) {
    int idx = blockIdx.x * blockDim.x + threadIdx.x;
    if (idx < F * F) {
        int f = idx >> 7, g = idx & (F - 1);
        g_Wt[idx] = Wm[g * F + f];
    }
    if (idx < n_atoms) g_cnt[idx] = 0;
}

// ---------------------------------------------------------------------------
// K2: histogram of idx_i + record within-bin position
// ---------------------------------------------------------------------------
__global__ void hist_kernel(const int* __restrict__ pl, int n_pairs) {
    int p = blockIdx.x * blockDim.x + threadIdx.x;
    if (p < n_pairs) g_pos[p] = atomicAdd(&g_cnt[pl[p]], 1);
}

// ---------------------------------------------------------------------------
// K3: exclusive scan over g_cnt -> g_off (single block)
// ---------------------------------------------------------------------------
__global__ void scan_kernel(int n_atoms) {
    __shared__ int ssum[SCAN_THREADS];
    int t = threadIdx.x;
    int base = t * SCAN_PER;
    int local[SCAN_PER];
    int s = 0;
#pragma unroll
    for (int k = 0; k < SCAN_PER; k++) {
        int idx = base + k;
        int v = (idx < n_atoms) ? g_cnt[idx] : 0;
        local[k] = s;
        s += v;
    }
    ssum[t] = s;
    __syncthreads();
    for (int d = 1; d < SCAN_THREADS; d <<= 1) {
        int x = (t >= d) ? ssum[t - d] : 0;
        __syncthreads();
        ssum[t] += x;
        __syncthreads();
    }
    int excl = (t > 0) ? ssum[t - 1] : 0;
#pragma unroll
    for (int k = 0; k < SCAN_PER; k++) {
        int idx = base + k;
        if (idx < n_atoms) g_off[idx] = excl + local[k];
    }
}

// ---------------------------------------------------------------------------
// K4: scatter pairs into bins — NO atomics (position precomputed in hist);
// records store PRE-SCALED (u*c, c)
// ---------------------------------------------------------------------------
__global__ void scatter_kernel(const int* __restrict__ pl,
                               const float* __restrict__ cut,
                               const float* __restrict__ rij,
                               int n_pairs) {
    int p = blockIdx.x * blockDim.x + threadIdx.x;
    if (p >= n_pairs) return;
    int   i = pl[p];
    int   j = pl[n_pairs + p];
    float c = cut[p];
    float r0 = rij[3 * p + 0];
    float r1 = rij[3 * p + 1];
    float r2 = rij[3 * p + 2];
    float s = rsqrtf(r0 * r0 + r1 * r1 + r2 * r2) * c;
    int pos = g_off[i] + g_pos[p];
    g_recJ[pos] = j;
    g_recU[pos] = make_float4(r0 * s, r1 * s, r2 * s, c);
}

// ---------------------------------------------------------------------------
// K5: gather. One warp per atom. Records staged in smem (LDS broadcast);
// accumulation in packed f32x2; 4-wide unrolled A prefetch.
// ---------------------------------------------------------------------------
struct Acc2 { u64 r0, r1, x0, x1, y0, y1, z0, z1; };

__device__ __forceinline__ void acc2(const float4& u, const ulonglong2& a, Acc2& s) {
    u64 cc = pack64(u.w, u.w);
    u64 xx = pack64(u.x, u.x);
    u64 yy = pack64(u.y, u.y);
    u64 zz = pack64(u.z, u.z);
    u64 w0 = mul2(cc, a.x);
    u64 w1 = mul2(cc, a.y);
    s.r0 = add2(s.r0, w0);  s.r1 = add2(s.r1, w1);
    FMA2(s.x0, xx, a.x);    // NOTE: x-channel uses pre-scaled u.x (= ux*c)
    FMA2(s.x1, xx, a.y);
    FMA2(s.y0, yy, a.x);
    FMA2(s.y1, yy, a.y);
    FMA2(s.z0, zz, a.x);
    FMA2(s.z1, zz, a.y);
}

__global__ __launch_bounds__(256)
void gather_kernel(const ulonglong2* __restrict__ A2,
                   float* __restrict__ out, int n_atoms) {
    __shared__ int    sJ[8][32];
    __shared__ float4 sU[8][32];

    int warp = threadIdx.x >> 5, lane = threadIdx.x & 31;
    int w = blockIdx.x * 8 + warp;
    if (w >= n_atoms) return;
    int n = g_cnt[w];
    int base = g_off[w];

    Acc2 s = {};

    for (int c0 = 0; c0 < n; c0 += 32) {
        int m = n - c0; if (m > 32) m = 32;
        if (lane < m) {
            sJ[warp][lane] = g_recJ[base + c0 + lane];
            sU[warp][lane] = g_recU[base + c0 + lane];
        }
        __syncwarp();
        int k = 0;
        for (; k + 4 <= m; k += 4) {
            int j0 = sJ[warp][k + 0];
            int j1 = sJ[warp][k + 1];
            int j2 = sJ[warp][k + 2];
            int j3 = sJ[warp][k + 3];
            ulonglong2 a0 = __ldg(&A2[j0 * F4 + lane]);
            ulonglong2 a1 = __ldg(&A2[j1 * F4 + lane]);
            ulonglong2 a2 = __ldg(&A2[j2 * F4 + lane]);
            ulonglong2 a3 = __ldg(&A2[j3 * F4 + lane]);
            float4 u0 = sU[warp][k + 0];
            float4 u1 = sU[warp][k + 1];
            float4 u2 = sU[warp][k + 2];
            float4 u3 = sU[warp][k + 3];
            acc2(u0, a0, s); acc2(u1, a1, s); acc2(u2, a2, s); acc2(u3, a3, s);
        }
        for (; k < m; k++) {
            int j0 = sJ[warp][k];
            ulonglong2 a0 = __ldg(&A2[j0 * F4 + lane]);
            float4 u0 = sU[warp][k];
            acc2(u0, a0, s);
        }
        __syncwarp();
    }

    float2 p0, p1;
    // radial half of output
    p0 = unpack64(s.r0); p1 = unpack64(s.r1);
    *(float4*)(out + w * (2 * F) + F + lane * 4) = make_float4(p0.x, p0.y, p1.x, p1.y);
    p0 = unpack64(s.x0); p1 = unpack64(s.x1);
    g_V[(w * 3 + 0) * F4 + lane] = make_float4(p0.x, p0.y, p1.x, p1.y);
    p0 = unpack64(s.y0); p1 = unpack64(s.y1);
    g_V[(w * 3 + 1) * F4 + lane] = make_float4(p0.x, p0.y, p1.x, p1.y);
    p0 = unpack64(s.z0); p1 = unpack64(s.z1);
    g_V[(w * 3 + 2) * F4 + lane] = make_float4(p0.x, p0.y, p1.x, p1.y);
}

// ---------------------------------------------------------------------------
// K6: fused GEMM + norm. 512 threads, 32 atoms/tile -> 16 warps/SM (2x R4
// occupancy at 1 block/SM). Thread = (atom = t&31, colgroup = t>>5 -> 8 cols);
// 3 channel rows per thread in f32x2 accumulators; norm+bias in-register.
// ---------------------------------------------------------------------------
__global__ __launch_bounds__(GT)
void gemm_norm_kernel(const float* __restrict__ bias,
                      float* __restrict__ out, int n_atoms) {
    extern __shared__ char smraw[];
    float* Ws = (float*)smraw;                        // [F][F] floats (64KB)
    u64*   VsU = (u64*)(smraw + F * F * 4);           // [96][VS_STRIDE] dup (v,v)

    int t = threadIdx.x;
    int ga = t & 31;            // atom in tile (0..31)
    int cg = t >> 5;            // col group (0..15) -> cols cg*8..+7
    const ulonglong2* WsU2 = (const ulonglong2*)Ws;   // row stride 32 ull2

    {
        const float4* src = (const float4*)g_Wt;
        float4* dst = (float4*)Ws;
        for (int k = t; k < F * F / 4; k += GT) dst[k] = src[k];
    }
    __syncthreads();

    int nrows3 = n_atoms * 3;
    int tiles = (n_atoms + GA - 1) / GA;
    for (int tile = blockIdx.x; tile < tiles; tile += gridDim.x) {
        int row0 = tile * GA * 3;

        // load V rows to regs first (overlaps previous tile's compute)
        float4 vst[6];
#pragma unroll
        for (int r = 0; r < 6; r++) {
            int idx = t + r * GT;            // 0..3071
            int row = idx >> 5, f4 = idx & 31;
            int grow = row0 + row;
            vst[r] = (grow < nrows3)
                       ? __ldg(&g_V[grow * F4 + f4])
                       : make_float4(0.f, 0.f, 0.f, 0.f);
        }
        __syncthreads();
#pragma unroll
        for (int r = 0; r < 6; r++) {
            int idx = t + r * GT;
            int row = idx >> 5, f4 = idx & 31;
            ulonglong2 q0, q1;
            q0.x = pack64(vst[r].x, vst[r].x);
            q0.y = pack64(vst[r].y, vst[r].y);
            q1.x = pack64(vst[r].z, vst[r].z);
            q1.y = pack64(vst[r].w, vst[r].w);
            *(ulonglong2*)&VsU[row * VS_STRIDE + f4 * 4]     = q0;
            *(ulonglong2*)&VsU[row * VS_STRIDE + f4 * 4 + 2] = q1;
        }
        __syncthreads();

        u64 acc[3][4] = {};
#pragma unroll 4
        for (int f = 0; f < F; f += 2) {
            ulonglong2 wa0 = WsU2[f * 32 + cg * 2];
            ulonglong2 wa1 = WsU2[f * 32 + cg * 2 + 1];
            ulonglong2 wb0 = WsU2[(f + 1) * 32 + cg * 2];
            ulonglong2 wb1 = WsU2[(f + 1) * 32 + cg * 2 + 1];
#pragma unroll
            for (int c = 0; c < 3; c++) {
                ulonglong2 v = *(const ulonglong2*)&VsU[(ga * 3 + c) * VS_STRIDE + f];
                FMA2(acc[c][0], v.x, wa0.x);
                FMA2(acc[c][1], v.x, wa0.y);
                FMA2(acc[c][2], v.x, wa1.x);
                FMA2(acc[c][3], v.x, wa1.y);
                FMA2(acc[c][0], v.y, wb0.x);
                FMA2(acc[c][1], v.y, wb0.y);
                FMA2(acc[c][2], v.y, wb1.x);
                FMA2(acc[c][3], v.y, wb1.y);
            }
        }

        int atom = tile * GA + ga;
        if (atom < n_atoms) {
            float cnt = (float)g_cnt[atom];
            float4 bv0 = __ldg((const float4*)&bias[cg * 8]);
            float4 bv1 = __ldg((const float4*)&bias[cg * 8 + 4]);
            float ob[8], bb[8];
            bb[0] = bv0.x * cnt; bb[1] = bv0.y * cnt; bb[2] = bv0.z * cnt; bb[3] = bv0.w * cnt;
            bb[4] = bv1.x * cnt; bb[5] = bv1.y * cnt; bb[6] = bv1.z * cnt; bb[7] = bv1.w * cnt;
#pragma unroll
            for (int q = 0; q < 4; q++) {
                float2 vx = unpack64(acc[0][q]);
                float2 vy = unpack64(acc[1][q]);
                float2 vz = unpack64(acc[2][q]);
                float x0 = vx.x + bb[2 * q], y0 = vy.x + bb[2 * q], z0 = vz.x + bb[2 * q];
                float x1 = vx.y + bb[2 * q + 1], y1 = vy.y + bb[2 * q + 1], z1 = vz.y + bb[2 * q + 1];
                ob[2 * q]     = sqrtf(x0 * x0 + y0 * y0 + z0 * z0 + 1e-12f);
                ob[2 * q + 1] = sqrtf(x1 * x1 + y1 * y1 + z1 * z1 + 1e-12f);
            }
            float* o = &out[atom * (2 * F) + cg * 8];
            *(float4*)o       = make_float4(ob[0], ob[1], ob[2], ob[3]);
            *(float4*)(o + 4) = make_float4(ob[4], ob[5], ob[6], ob[7]);
        }
    }
}

// ---------------------------------------------------------------------------
// Launch
// ---------------------------------------------------------------------------
extern "C" void kernel_launch(void* const* d_in, const int* in_sizes, int n_in,
                              void* d_out, int out_size) {
    const float* A   = (const float*)d_in[0];   // [N, F]
    const int*   pl  = (const int*)  d_in[1];   // [2, P]
    const float* cut = (const float*)d_in[2];   // [P, 1]
    const float* rij = (const float*)d_in[3];   // [P, 3]
    const float* Wm  = (const float*)d_in[4];   // [F, F]
    const float* b   = (const float*)d_in[5];   // [F]
    float* out = (float*)d_out;                 // [N, 2F]

    int n_atoms = in_sizes[0] / F;
    int n_pairs = in_sizes[2];

    int init_n = (n_atoms > F * F) ? n_atoms : F * F;
    init_kernel<<<(init_n + 255) / 256, 256>>>(Wm, n_atoms);

    hist_kernel<<<(n_pairs + 255) / 256, 256>>>(pl, n_pairs);

    scan_kernel<<<1, SCAN_THREADS>>>(n_atoms);

    scatter_kernel<<<(n_pairs + 255) / 256, 256>>>(pl, cut, rij, n_pairs);

    gather_kernel<<<(n_atoms + 7) / 8, 256>>>((const ulonglong2*)A, out, n_atoms);

    {
        int smem = F * F * 4 + 3 * GA * VS_STRIDE * 8;   // 64KB + 97.5KB
        cudaFuncSetAttribute(gemm_norm_kernel,
                             cudaFuncAttributeMaxDynamicSharedMemorySize, smem);
        gemm_norm_kernel<<<296, GT, smem>>>(b, out, n_atoms);
    }
}